// round 7
// baseline (speedup 1.0000x reference)
#include <cuda_runtime.h>

#define KNN 16
#define NPTS 8192
#define DIMS 64
#define TILE 128
#define AST 65    // ull stride per-d for As_T  (64 row-pairs + 1 pad)
#define BST 131   // ull stride per-d for BsDup (128 cols + 3 pad)
#define DST 132   // float stride for Ds: epilogue bank = 8*wy+wx+const (free)
#define NTHR 512

// packed fp32x2 FMA (sm_103a): acc = a*b + acc elementwise on 2 fp32 lanes
#define FMA2(acc, a, b) \
    asm("fma.rn.f32x2 %0, %1, %2, %0;" : "+l"(acc) : "l"(a), "l"(b))

__global__ __launch_bounds__(NTHR, 1)
void knn_tiled3(const float* __restrict__ x, float* __restrict__ out) {
    extern __shared__ unsigned long long smem_u64[];
    unsigned long long* AsT = smem_u64;                 // [64][AST] ull
    unsigned long long* BsD = AsT + DIMS * AST;         // [64][BST] ull
    float* Ds  = (float*)(BsD + DIMS * BST);            // [128][DST]
    float* sqA = Ds + TILE * DST;                       // 128
    float* sqB = sqA + TILE;                            // 128
    float* kds = sqB + TILE;                            // 128*16
    int*   kis = (int*)(kds + TILE * KNN);              // 128*16
    float* AsTf = (float*)AsT;                          // [d][row], row stride 2*AST

    const int tid    = threadIdx.x;
    const int lane   = tid & 31;
    const int warp   = tid >> 5;       // 0..15
    const int wy     = lane >> 3;      // 0..3
    const int wx     = lane & 7;       // 0..7
    const int warp_y = warp >> 2;      // 0..3
    const int warp_x = warp & 3;       // 0..3
    const int batch  = blockIdx.y;
    const int row0   = blockIdx.x * TILE;
    const float* xb  = x + (size_t)batch * NPTS * DIMS;

    const float INF = __int_as_float(0x7f800000);

    float kth = INF;
    if (tid < TILE) {
        #pragma unroll
        for (int j = 0; j < KNN; j++) { kds[tid * KNN + j] = INF; kis[tid * KNN + j] = 0; }
    }

    // ---- A tile: transposed store As_T[d][row] ----
    for (int i = tid; i < TILE * (DIMS / 4); i += NTHR) {
        const int d4 = i >> 7;         // 0..15
        const int r  = i & 127;        // consecutive per lane -> STS conflict-free
        float4 v = *(const float4*)&xb[(size_t)(row0 + r) * DIMS + 4 * d4];
        AsTf[(4 * d4 + 0) * (2 * AST) + r] = v.x;
        AsTf[(4 * d4 + 1) * (2 * AST) + r] = v.y;
        AsTf[(4 * d4 + 2) * (2 * AST) + r] = v.z;
        AsTf[(4 * d4 + 3) * (2 * AST) + r] = v.w;
    }
    // sqA: sequential fma chain (matches FMA2 lane chains -> self-dist == 0)
    if (tid < TILE) {
        float s = 0.f;
        const float* p = &xb[(size_t)(row0 + tid) * DIMS];
        #pragma unroll
        for (int d4 = 0; d4 < 16; d4++) {
            float4 v = *(const float4*)&p[4 * d4];
            s = fmaf(v.x, v.x, s); s = fmaf(v.y, v.y, s);
            s = fmaf(v.z, v.z, s); s = fmaf(v.w, v.w, s);
        }
        sqA[tid] = s;
    }

    const int prbase = 16 * warp_y + wy;   // pairs: prbase + 4*p, p=0..3
    const int cbase  = 32 * warp_x + wx;   // cols:  cbase + 8*n, n=0..3

    for (int t = 0; t < NPTS / TILE; t++) {
        const int col0 = t * TILE;

        __syncthreads();   // prev tile consumed; A tile ready on t=0

        // ---- B tile: duplicated transpose BsDup[d][c] = {v,v} ----
        for (int i = tid; i < TILE * (DIMS / 4); i += NTHR) {
            const int d4 = i >> 7;
            const int r  = i & 127;
            float4 v = *(const float4*)&xb[(size_t)(col0 + r) * DIMS + 4 * d4];
            unsigned long long dx, dy, dz, dw;
            asm("mov.b64 %0, {%1, %1};" : "=l"(dx) : "f"(v.x));
            asm("mov.b64 %0, {%1, %1};" : "=l"(dy) : "f"(v.y));
            asm("mov.b64 %0, {%1, %1};" : "=l"(dz) : "f"(v.z));
            asm("mov.b64 %0, {%1, %1};" : "=l"(dw) : "f"(v.w));
            BsD[(4 * d4 + 0) * BST + r] = dx;
            BsD[(4 * d4 + 1) * BST + r] = dy;
            BsD[(4 * d4 + 2) * BST + r] = dz;
            BsD[(4 * d4 + 3) * BST + r] = dw;
        }
        if (tid < TILE) {
            float s = 0.f;
            const float* p = &xb[(size_t)(col0 + tid) * DIMS];
            #pragma unroll
            for (int d4 = 0; d4 < 16; d4++) {
                float4 v = *(const float4*)&p[4 * d4];
                s = fmaf(v.x, v.x, s); s = fmaf(v.y, v.y, s);
                s = fmaf(v.z, v.z, s); s = fmaf(v.w, v.w, s);
            }
            sqB[tid] = s;
        }
        __syncthreads();   // BsD + sqB visible

        // ---- mainloop: 128x128x64, M-packed f32x2, 4x4 fragment ----
        unsigned long long acc2[4][4];
        #pragma unroll
        for (int p = 0; p < 4; p++)
            #pragma unroll
            for (int n = 0; n < 4; n++) acc2[p][n] = 0ull;

        const unsigned long long* aptr = AsT + prbase;
        const unsigned long long* bptr = BsD + cbase;

        #pragma unroll 4
        for (int d = 0; d < DIMS; d++) {
            unsigned long long a2[4], bd[4];
            #pragma unroll
            for (int p = 0; p < 4; p++) a2[p] = aptr[d * AST + 4 * p];
            #pragma unroll
            for (int n = 0; n < 4; n++) bd[n] = bptr[d * BST + 8 * n];
            #pragma unroll
            for (int p = 0; p < 4; p++)
                #pragma unroll
                for (int n = 0; n < 4; n++) FMA2(acc2[p][n], a2[p], bd[n]);
        }

        // ---- epilogue: dist into Ds (bank = 8*wy+wx+const -> conflict-free) ----
        #pragma unroll
        for (int p = 0; p < 4; p++) {
            const int r0 = 2 * (prbase + 4 * p);
            const float sa0 = sqA[r0], sa1 = sqA[r0 + 1];
            #pragma unroll
            for (int n = 0; n < 4; n++) {
                const int c = cbase + 8 * n;
                float lo, hi;
                asm("mov.b64 {%0, %1}, %2;" : "=f"(lo), "=f"(hi) : "l"(acc2[p][n]));
                const float sb = sqB[c];
                Ds[r0 * DST + c]       = (sa0 - 2.f * lo) + sb;
                Ds[(r0 + 1) * DST + c] = (sa1 - 2.f * hi) + sb;
            }
        }
        __syncthreads();   // Ds visible

        // ---- selection: thread t (<128) owns row t; stable ascending scan ----
        if (tid < TILE) {
            const int base = tid * KNN;
            #pragma unroll 4
            for (int c4 = 0; c4 < TILE / 4; c4++) {
                float4 dv = *(float4*)&Ds[tid * DST + 4 * c4];
                #pragma unroll
                for (int e = 0; e < 4; e++) {
                    const float d = (e == 0) ? dv.x : (e == 1) ? dv.y
                                  : (e == 2) ? dv.z : dv.w;
                    if (d < kth) {                      // rare
                        int j = KNN - 1;
                        while (j > 0 && kds[base + j - 1] > d) {
                            kds[base + j] = kds[base + j - 1];
                            kis[base + j] = kis[base + j - 1];
                            j--;
                        }
                        kds[base + j] = d;
                        kis[base + j] = col0 + 4 * c4 + e;
                        kth = kds[base + KNN - 1];
                    }
                }
            }
        }
        // loop-top __syncthreads separates selection from next B-store
    }

    // ---- output (float): out[0]=nn_idx (B,N,K), out[1]=center_idx ----
    if (tid < TILE) {
        float* out_nn = out;
        float* out_c  = out + 2 * NPTS * KNN;
        const int grow = row0 + tid;
        const size_t obase = ((size_t)batch * NPTS + grow) * KNN;
        #pragma unroll
        for (int j = 0; j < KNN; j++) {
            out_nn[obase + j] = (float)kis[tid * KNN + j];
            out_c [obase + j] = (float)grow;
        }
    }
}

extern "C" void kernel_launch(void* const* d_in, const int* in_sizes, int n_in,
                              void* d_out, int out_size) {
    const float* x = (const float*)d_in[0];
    float* out = (float*)d_out;

    const size_t smem_bytes =
        (size_t)(DIMS * AST + DIMS * BST) * 8 +
        (size_t)(TILE * DST + 2 * TILE + TILE * KNN) * 4 +
        (size_t)TILE * KNN * 4;

    cudaFuncSetAttribute(knn_tiled3,
                         cudaFuncAttributeMaxDynamicSharedMemorySize,
                         (int)smem_bytes);

    dim3 grid(NPTS / TILE, 2);
    knn_tiled3<<<grid, NTHR, smem_bytes>>>(x, out);
}

// round 9
// speedup vs baseline: 1.3154x; 1.3154x over previous
#include <cuda_runtime.h>

#define KNN 16
#define NPTS 8192
#define DIMS 64
#define TILE 128
#define NTHR 512
#define APITCH 65     // ull per d-row of AsP: 64 row-pairs + 1 pad (conflict-free)
#define BPITCH 132    // floats per d-row of Bs (128 + 4; mult of 4 for cp.async 16B)
#define DST 132       // Ds stride: epilogue bank = 8*wy+wx+const -> conflict-free

__device__ float g_xT[2][DIMS][NPTS];   // transposed points
__device__ float g_nrm[2][NPTS];        // squared norms

#define FMA2(acc, a, b) \
    asm("fma.rn.f32x2 %0, %1, %2, %0;" : "+l"(acc) : "l"(a), "l"(b))

#define CP_ASYNC16(smem_u32, gptr) \
    asm volatile("cp.async.ca.shared.global [%0], [%1], 16;" \
                 :: "r"(smem_u32), "l"(gptr))
#define CP_COMMIT()  asm volatile("cp.async.commit_group;")
#define CP_WAIT0()   asm volatile("cp.async.wait_group 0;" ::: "memory")

// ---- pre-kernel: tiled transpose + norms (one-time, L2-resident data) ----
__global__ __launch_bounds__(256, 1)
void pre_kernel(const float* __restrict__ x) {
    __shared__ float s[TILE][DIMS + 1];
    const int b = blockIdx.y, n0 = blockIdx.x * TILE, tid = threadIdx.x;
    const float* xb = x + (size_t)b * NPTS * DIMS;

    for (int i = tid; i < TILE * (DIMS / 4); i += 256) {
        const int r = i >> 4, d4 = i & 15;
        float4 v = *(const float4*)&xb[(size_t)(n0 + r) * DIMS + 4 * d4];
        s[r][4 * d4 + 0] = v.x; s[r][4 * d4 + 1] = v.y;
        s[r][4 * d4 + 2] = v.z; s[r][4 * d4 + 3] = v.w;
    }
    __syncthreads();
    if (tid < TILE) {
        float sum = 0.f;
        #pragma unroll
        for (int d = 0; d < DIMS; d++) sum = fmaf(s[tid][d], s[tid][d], sum);
        g_nrm[b][n0 + tid] = sum;
    }
    for (int i = tid; i < DIMS * TILE; i += 256) {
        const int d = i >> 7, c = i & 127;       // lanes: consecutive c -> coalesced STG
        g_xT[b][d][n0 + c] = s[c][d];            // LDS stride 65 -> conflict-free
    }
}

// ---- main kernel ----
__global__ __launch_bounds__(NTHR, 1)
void knn4(const float* __restrict__ x, float* __restrict__ out) {
    extern __shared__ unsigned long long smem_u64[];
    unsigned long long* AsP = smem_u64;                    // [64][APITCH] ull
    float* Bs0 = (float*)(AsP + DIMS * APITCH);            // [64][BPITCH]
    float* Bs1 = Bs0 + DIMS * BPITCH;                      // [64][BPITCH]
    float* Ds  = Bs1 + DIMS * BPITCH;                      // [128][DST]
    float* kds = Ds + TILE * DST;                          // 128*16
    int*   kis = (int*)(kds + TILE * KNN);                 // 128*16
    float* AsPf = (float*)AsP;                             // [d][r], d-row = 130 floats

    const int tid    = threadIdx.x;
    const int lane   = tid & 31;
    const int warp   = tid >> 5;       // 0..15
    const int wy     = lane >> 3;      // 0..3
    const int wx     = lane & 7;       // 0..7
    const int warp_y = warp >> 2;      // 0..3
    const int warp_x = warp & 3;       // 0..3
    const int batch  = blockIdx.y;
    const int row0   = blockIdx.x * TILE;

    const float INF = __int_as_float(0x7f800000);
    float kth = INF;
    if (tid < TILE) {
        #pragma unroll
        for (int j = 0; j < KNN; j++) { kds[tid * KNN + j] = INF; kis[tid * KNN + j] = 0; }
    }

    // A tile: AsPf[d][r] = xT[b][d][row0+r]  (coalesced LDG, conflict-free STS)
    for (int i = tid; i < DIMS * TILE; i += NTHR) {
        const int d = i >> 7, r = i & 127;
        AsPf[d * (2 * APITCH) + r] = g_xT[batch][d][row0 + r];
    }

    const int prbase = 16 * warp_y + wy;   // row-pairs: prbase + 4*p, p=0..3 (0..63)
    const int cbase  = 32 * warp_x + wx;   // cols:      cbase + 8*n,  n=0..3

    // per-thread row norms (rows 2*(prbase+4p), +1)
    float sa0[4], sa1[4];
    #pragma unroll
    for (int p = 0; p < 4; p++) {
        const int r0 = 2 * (prbase + 4 * p);
        sa0[p] = g_nrm[batch][row0 + r0];
        sa1[p] = g_nrm[batch][row0 + r0 + 1];
    }

    // prefetch B(0) into Bs0
    {
        float* dst = Bs0;
        for (int k = 0; k < 4; k++) {
            const int idx = tid + k * NTHR;          // 0..2047 (64 d x 32 c4)
            const int d = idx >> 5, c4 = idx & 31;
            CP_ASYNC16((unsigned)__cvta_generic_to_shared(&dst[d * BPITCH + 4 * c4]),
                       &g_xT[batch][d][0 + 4 * c4]);
        }
        CP_COMMIT();
    }

    float* cur = Bs0;
    float* nxt = Bs1;

    for (int t = 0; t < NPTS / TILE; t++) {
        const int col0 = t * TILE;

        CP_WAIT0();          // B(t) landed
        __syncthreads();     // B(t)+A visible to all; selection(t-1) done (Ds free)

        // launch B(t+1) copy — overlaps with GEMM(t)
        if (t + 1 < NPTS / TILE) {
            const int ncol0 = col0 + TILE;
            for (int k = 0; k < 4; k++) {
                const int idx = tid + k * NTHR;
                const int d = idx >> 5, c4 = idx & 31;
                CP_ASYNC16((unsigned)__cvta_generic_to_shared(&nxt[d * BPITCH + 4 * c4]),
                           &g_xT[batch][d][ncol0 + 4 * c4]);
            }
            CP_COMMIT();
        }

        // candidate norms for epilogue (L2-hit; issued early to hide latency)
        float sb[4];
        #pragma unroll
        for (int n = 0; n < 4; n++) sb[n] = g_nrm[batch][col0 + cbase + 8 * n];

        // ---- GEMM: 128x128x64, M-packed f32x2, 4 pairs x 4 cols ----
        unsigned long long acc2[4][4];
        #pragma unroll
        for (int p = 0; p < 4; p++)
            #pragma unroll
            for (int n = 0; n < 4; n++) acc2[p][n] = 0ull;

        const unsigned long long* aptr = AsP + prbase;
        const float* bptr = cur + cbase;

        #pragma unroll 8
        for (int d = 0; d < DIMS; d++) {
            unsigned long long a2[4], bd[4];
            #pragma unroll
            for (int p = 0; p < 4; p++) a2[p] = aptr[d * APITCH + 4 * p];
            #pragma unroll
            for (int n = 0; n < 4; n++) {
                const float bv = bptr[d * BPITCH + 8 * n];
                asm("mov.b64 %0, {%1, %1};" : "=l"(bd[n]) : "f"(bv));
            }
            #pragma unroll
            for (int p = 0; p < 4; p++)
                #pragma unroll
                for (int n = 0; n < 4; n++) FMA2(acc2[p][n], a2[p], bd[n]);
        }

        // ---- epilogue: dist -> Ds (conflict-free banks) ----
        #pragma unroll
        for (int p = 0; p < 4; p++) {
            const int r0 = 2 * (prbase + 4 * p);
            #pragma unroll
            for (int n = 0; n < 4; n++) {
                const int c = cbase + 8 * n;
                float lo, hi;
                asm("mov.b64 {%0, %1}, %2;" : "=f"(lo), "=f"(hi) : "l"(acc2[p][n]));
                Ds[r0 * DST + c]       = (sa0[p] - 2.f * lo) + sb[n];
                Ds[(r0 + 1) * DST + c] = (sa1[p] - 2.f * hi) + sb[n];
            }
        }
        __syncthreads();     // Ds visible

        // ---- selection: thread t<128 owns row t; stable ascending scan ----
        if (tid < TILE) {
            const int base = tid * KNN;
            #pragma unroll 4
            for (int c4 = 0; c4 < TILE / 4; c4++) {
                float4 dv = *(float4*)&Ds[tid * DST + 4 * c4];
                const float mn = fminf(fminf(dv.x, dv.y), fminf(dv.z, dv.w));
                if (mn < kth) {                          // rare: branch per quad
                    #pragma unroll
                    for (int e = 0; e < 4; e++) {
                        const float d = (e == 0) ? dv.x : (e == 1) ? dv.y
                                      : (e == 2) ? dv.z : dv.w;
                        if (d < kth) {
                            int j = KNN - 1;
                            while (j > 0 && kds[base + j - 1] > d) {
                                kds[base + j] = kds[base + j - 1];
                                kis[base + j] = kis[base + j - 1];
                                j--;
                            }
                            kds[base + j] = d;
                            kis[base + j] = col0 + 4 * c4 + e;
                            kth = kds[base + KNN - 1];
                        }
                    }
                }
            }
        }
        // swap buffers; loop-top barrier separates selection from next epilogue
        float* tmp = cur; cur = nxt; nxt = tmp;
    }

    // ---- output (float): out[0]=nn_idx (B,N,K), out[1]=center_idx ----
    if (tid < TILE) {
        float* out_nn = out;
        float* out_c  = out + 2 * NPTS * KNN;
        const int grow = row0 + tid;
        const size_t obase = ((size_t)batch * NPTS + grow) * KNN;
        #pragma unroll
        for (int j = 0; j < KNN; j++) {
            out_nn[obase + j] = (float)kis[tid * KNN + j];
            out_c [obase + j] = (float)grow;
        }
    }
}

extern "C" void kernel_launch(void* const* d_in, const int* in_sizes, int n_in,
                              void* d_out, int out_size) {
    const float* x = (const float*)d_in[0];
    float* out = (float*)d_out;

    const size_t smem_bytes =
        (size_t)DIMS * APITCH * 8 +              // AsP  (33,280)
        (size_t)2 * DIMS * BPITCH * 4 +          // Bs0/Bs1 (67,584)
        (size_t)TILE * DST * 4 +                 // Ds (67,584)
        (size_t)TILE * KNN * 4 * 2;              // kds + kis (16,384)

    cudaFuncSetAttribute(knn4,
                         cudaFuncAttributeMaxDynamicSharedMemorySize,
                         (int)smem_bytes);

    dim3 pgrid(NPTS / TILE, 2);
    pre_kernel<<<pgrid, 256>>>(x);

    dim3 grid(NPTS / TILE, 2);
    knn4<<<grid, NTHR, smem_bytes>>>(x, out);
}